// round 12
// baseline (speedup 1.0000x reference)
#include <cuda_runtime.h>
#include <cuda_fp16.h>
#include <cstdint>
#include <cstddef>

#define B_ 32
#define T_ 2048
#define D_ 512
#define U_ 512
#define CTX_OFF (B_*D_)   // context at [0:16384], attn at [16384:]

// score-GEMM tiling: fp16 mma.sync m16n8k16, 256 threads, warp tile 64x32
#define BM 128
#define BN 128
#define BK 64
#define NKC (D_/BK)       // 8 chunks
#define N_UT (U_/BN)      // 4 u-tiles
#define LDH 72            // padded row stride in halfs (144B) — ldmatrix conflict-free

// dynamic smem for score kernel
#define SM_QP    0                      // 128 floats
#define SM_VW    512                    // 128 floats
#define SM_RED   1024                   // ssum[4][128] floats = 2048B
#define SM_A0    4096
#define SM_TILE  (BM*LDH*2)             // 18432 B (A or B)
#define SM_STAGE (2*SM_TILE)            // 36864 B
#define SM_TOTAL (SM_A0 + 2*SM_STAGE)   // 77824 B -> 2 CTAs/SM

// ---------------- device scratch ----------------
__device__ __half g_vhalf[(size_t)B_*T_*D_];   // fp16 copy of values (67 MB)
__device__ __half g_W2Th[U_*D_];               // W2^T in fp16: [u][d]
__device__ float  g_qpart[4*B_*U_];
__device__ float  g_pscore[N_UT*B_*T_];

// ---------------- helpers ----------------
__device__ __forceinline__ uint32_t h2_as_u32(__half2 h){
    uint32_t u; __builtin_memcpy(&u, &h, 4); return u;
}
__device__ __forceinline__ float tanh_fast(float x){
    float r; asm("tanh.approx.f32 %0, %1;" : "=f"(r) : "f"(x)); return r;
}
__device__ __forceinline__ void cp16(uint32_t smem, const void* gmem){
    asm volatile("cp.async.cg.shared.global [%0], [%1], 16;\n" :: "r"(smem), "l"(gmem));
}
__device__ __forceinline__ void ldm_x4(uint32_t r[4], uint32_t addr){
    asm volatile("ldmatrix.sync.aligned.m8n8.x4.shared.b16 {%0,%1,%2,%3}, [%4];"
        : "=r"(r[0]), "=r"(r[1]), "=r"(r[2]), "=r"(r[3]) : "r"(addr));
}
__device__ __forceinline__ void mma_f16(float c[4], const uint32_t a[4],
                                        uint32_t b0, uint32_t b1){
    asm volatile(
        "mma.sync.aligned.m16n8k16.row.col.f32.f16.f16.f32 "
        "{%0,%1,%2,%3}, {%4,%5,%6,%7}, {%8,%9}, {%0,%1,%2,%3};\n"
        : "+f"(c[0]), "+f"(c[1]), "+f"(c[2]), "+f"(c[3])
        : "r"(a[0]), "r"(a[1]), "r"(a[2]), "r"(a[3]),
          "r"(b0), "r"(b1));
}

// ---------------- kernel 0: values fp32 -> fp16 ----------------
__global__ __launch_bounds__(256) void convert_kernel(const float4* __restrict__ v)
{
    const size_t i = (size_t)blockIdx.x*256 + threadIdx.x;   // 8 floats each
    const float4 f0 = v[2*i], f1 = v[2*i+1];
    uint4 o;
    o.x = h2_as_u32(__floats2half2_rn(f0.x, f0.y));
    o.y = h2_as_u32(__floats2half2_rn(f0.z, f0.w));
    o.z = h2_as_u32(__floats2half2_rn(f1.x, f1.y));
    o.w = h2_as_u32(__floats2half2_rn(f1.z, f1.w));
    ((uint4*)g_vhalf)[i] = o;
}

// ---------------- kernel 1: qproj partials over D-slices ----------------
__global__ __launch_bounds__(512) void qproj_kernel(
    const float* __restrict__ query, const float* __restrict__ W1)
{
    const int b = blockIdx.x, sp = blockIdx.y, tid = threadIdx.x;
    __shared__ float sq[128];
    if (tid < 128) sq[tid] = query[b*D_ + sp*128 + tid];
    __syncthreads();
    const float* w = W1 + (size_t)(sp*128)*U_ + tid;
    float acc = 0.f;
    #pragma unroll 8
    for (int d = 0; d < 128; d++)
        acc += sq[d] * w[(size_t)d*U_];
    g_qpart[(size_t)sp*(B_*U_) + b*U_ + tid] = acc;
}

// ---------------- kernel 1b: W2Th[u][d] = half(W2[d][u]); zero context ----------------
__global__ __launch_bounds__(256) void transpose_kernel(
    const float* __restrict__ W2, float* __restrict__ out)
{
    __shared__ float tile[32][33];
    const int bx = blockIdx.x*32, by = blockIdx.y*32;
    const int tx = threadIdx.x, ty = threadIdx.y;
    #pragma unroll
    for (int j = 0; j < 32; j += 8)
        tile[ty+j][tx] = W2[(size_t)(by+ty+j)*U_ + bx+tx];
    __syncthreads();
    #pragma unroll
    for (int j = 0; j < 32; j += 8)
        g_W2Th[(size_t)(bx+ty+j)*D_ + by+tx] = __float2half_rn(tile[tx][ty+j]);
    const int gid = (blockIdx.y*(U_/32) + blockIdx.x)*256 + ty*32 + tx;
    if (gid < CTX_OFF) out[gid] = 0.0f;
}

// ---------------- kernel 2: fused score GEMM (fp16 mma + ldmatrix, 64x32 warp tiles) ----------------
__global__ __launch_bounds__(256, 2) void score_kernel(
    const float* __restrict__ W1b, const float* __restrict__ W2b,
    const float* __restrict__ Vw)
{
    extern __shared__ __align__(1024) char smem[];
    float* sQP  = (float*)(smem + SM_QP);
    float* sVw  = (float*)(smem + SM_VW);
    float* ssum = (float*)(smem + SM_RED);

    const int tid = threadIdx.x;
    const int ut = blockIdx.x;
    const int t0 = blockIdx.y * BM;
    const int b  = blockIdx.z;
    const int u0 = ut * BN;
    const int warp = tid >> 5, lane = tid & 31;
    const int g = lane >> 2, tg = lane & 3;
    const int wm = warp >> 2, wn = warp & 3;     // 2 x 4 warps
    const int m0 = wm * 64,  n0 = wn * 32;

    if (tid < BN) {
        const int u = u0 + tid;
        sQP[tid] = g_qpart[u + b*U_] + g_qpart[B_*U_ + u + b*U_]
                 + g_qpart[2*B_*U_ + u + b*U_] + g_qpart[3*B_*U_ + u + b*U_]
                 + W1b[u] + W2b[u];
    } else {
        sVw[tid - BN] = Vw[u0 + tid - BN];
    }

    const __half* Abase = g_vhalf + ((size_t)b*T_ + t0) * D_;
    const __half* Bbase = g_W2Th + (size_t)u0 * D_;
    const uint32_t sA = (uint32_t)__cvta_generic_to_shared(smem + SM_A0);

    // ldmatrix per-lane addresses (byte offsets within tile)
    const int arow = m0 + (lane & 15);
    const int acol = (lane & 16) ? 8 : 0;
    const int brow = n0 + (lane & 7) + ((lane & 16) >> 1);
    const int bcol = lane & 8;
    const uint32_t aoff = (uint32_t)(arow*LDH + acol) * 2;
    const uint32_t boff = (uint32_t)(brow*LDH + bcol) * 2;

    float c[4][4][4];
    #pragma unroll
    for (int mi = 0; mi < 4; mi++)
        #pragma unroll
        for (int ni = 0; ni < 4; ni++)
            #pragma unroll
            for (int q = 0; q < 4; q++) c[mi][ni][q] = 0.f;

    // per stage: A 128 rows x 64 halfs (8 cp16/row) + B same; 256 threads x 4 iters
    #define LOADC(KC, S) do {                                                    \
        const uint32_t as_ = sA + (S)*SM_STAGE;                                  \
        const uint32_t bs_ = as_ + SM_TILE;                                      \
        _Pragma("unroll")                                                        \
        for (int j = 0; j < 4; j++) {                                            \
            int idx = tid + j*256, r = idx >> 3, cc = idx & 7;                   \
            cp16(as_ + r*(LDH*2) + cc*16, Abase + (size_t)r*D_ + (KC)*BK + cc*8);\
            cp16(bs_ + r*(LDH*2) + cc*16, Bbase + (size_t)r*D_ + (KC)*BK + cc*8);\
        }                                                                        \
        asm volatile("cp.async.commit_group;\n");                                \
    } while (0)

    LOADC(0, 0);
    LOADC(1, 1);

    for (int kc = 0; kc < NKC; kc++) {
        if (kc < NKC-1) asm volatile("cp.async.wait_group 1;\n");
        else            asm volatile("cp.async.wait_group 0;\n");
        __syncthreads();
        const int s = kc & 1;
        const uint32_t aAddr = sA + s*SM_STAGE + aoff;
        const uint32_t bAddr = sA + s*SM_STAGE + SM_TILE + boff;

        #pragma unroll
        for (int ks = 0; ks < BK; ks += 16) {
            uint32_t a[4][4], bb[2][4];
            ldm_x4(a[0],  aAddr + ks*2);
            ldm_x4(a[1],  aAddr + 16*LDH*2 + ks*2);
            ldm_x4(a[2],  aAddr + 32*LDH*2 + ks*2);
            ldm_x4(a[3],  aAddr + 48*LDH*2 + ks*2);
            ldm_x4(bb[0], bAddr + ks*2);
            ldm_x4(bb[1], bAddr + 16*LDH*2 + ks*2);
            #pragma unroll
            for (int mi = 0; mi < 4; mi++)
                #pragma unroll
                for (int ni = 0; ni < 4; ni++)
                    mma_f16(c[mi][ni], a[mi],
                            bb[ni>>1][2*(ni&1)], bb[ni>>1][2*(ni&1)+1]);
        }
        __syncthreads();
        if (kc + 2 < NKC) LOADC(kc + 2, s);
    }
    #undef LOADC

    // ---- epilogue: tanh + dot(Vw), reduce over u ----
    float rs[4][2] = {{0.f,0.f},{0.f,0.f},{0.f,0.f},{0.f,0.f}};
    #pragma unroll
    for (int mi = 0; mi < 4; mi++)
        #pragma unroll
        for (int ni = 0; ni < 4; ni++) {
            const int cN0 = n0 + ni*8 + 2*tg;
            #pragma unroll
            for (int h = 0; h < 2; h++)
                #pragma unroll
                for (int q = 0; q < 2; q++) {
                    float v = c[mi][ni][h*2 + q] + sQP[cN0 + q];
                    rs[mi][h] += tanh_fast(v) * sVw[cN0 + q];
                }
        }
    #pragma unroll
    for (int mi = 0; mi < 4; mi++)
        #pragma unroll
        for (int h = 0; h < 2; h++) {
            rs[mi][h] += __shfl_xor_sync(0xffffffffu, rs[mi][h], 1);
            rs[mi][h] += __shfl_xor_sync(0xffffffffu, rs[mi][h], 2);
        }
    if (tg == 0) {
        #pragma unroll
        for (int mi = 0; mi < 4; mi++)
            #pragma unroll
            for (int h = 0; h < 2; h++)
                ssum[wn*BM + m0 + mi*16 + h*8 + g] = rs[mi][h];
    }
    __syncthreads();
    if (tid < BM) {
        float s = ssum[tid] + ssum[BM + tid] + ssum[2*BM + tid] + ssum[3*BM + tid];
        g_pscore[(size_t)ut*(B_*T_) + b*T_ + t0 + tid] = s;
    }
}

// ---------------- kernel 3: softmax over T, write attn ----------------
__global__ __launch_bounds__(512) void softmax_kernel(
    const float* __restrict__ Vb, float* __restrict__ out)
{
    const int b = blockIdx.x, tid = threadIdx.x;
    __shared__ float red[512];
    float loc[4];
    const float vb = Vb[0];
    float mx = -1e30f;
    #pragma unroll
    for (int j = 0; j < 4; j++) {
        int t = tid + j*512;
        float s = vb;
        #pragma unroll
        for (int i = 0; i < N_UT; i++) s += g_pscore[i*(B_*T_) + b*T_ + t];
        loc[j] = s;
        mx = fmaxf(mx, s);
    }
    red[tid] = mx; __syncthreads();
    #pragma unroll
    for (int s = 256; s > 0; s >>= 1) {
        if (tid < s) red[tid] = fmaxf(red[tid], red[tid + s]);
        __syncthreads();
    }
    mx = red[0]; __syncthreads();
    float se = 0.f;
    #pragma unroll
    for (int j = 0; j < 4; j++) { loc[j] = __expf(loc[j] - mx); se += loc[j]; }
    red[tid] = se; __syncthreads();
    #pragma unroll
    for (int s = 256; s > 0; s >>= 1) {
        if (tid < s) red[tid] += red[tid + s];
        __syncthreads();
    }
    const float inv = 1.0f / red[0];
    #pragma unroll
    for (int j = 0; j < 4; j++)
        out[CTX_OFF + b*T_ + tid + j*512] = loc[j] * inv;
}

// ---------------- kernel 4: context = sum_t attn * values (fp16 values) ----------------
__global__ __launch_bounds__(512) void context_kernel(float* __restrict__ out)
{
    const int b = blockIdx.x, tid = threadIdx.x;
    const int t0 = blockIdx.y * 256;
    const int tl = tid >> 6;          // t-lane 0..7
    const int dt = tid & 63;          // d-group: 8 halfs each
    __shared__ float sa[256];
    __shared__ float4 sredA[512];
    __shared__ float4 sredB[512];
    if (tid < 256) sa[tid] = out[CTX_OFF + b*T_ + t0 + tid];
    __syncthreads();
    const uint4* vp = (const uint4*)(g_vhalf + ((size_t)b*T_ + t0)*D_) + dt;
    float4 aA = {0.f,0.f,0.f,0.f}, aB = {0.f,0.f,0.f,0.f};
    #pragma unroll 4
    for (int tt = tl; tt < 256; tt += 8) {
        const uint4 u = vp[(size_t)tt*(D_/8)];
        const float w = sa[tt];
        const float2 f0 = __half22float2(*(const __half2*)&u.x);
        const float2 f1 = __half22float2(*(const __half2*)&u.y);
        const float2 f2 = __half22float2(*(const __half2*)&u.z);
        const float2 f3 = __half22float2(*(const __half2*)&u.w);
        aA.x += w*f0.x; aA.y += w*f0.y; aA.z += w*f1.x; aA.w += w*f1.y;
        aB.x += w*f2.x; aB.y += w*f2.y; aB.z += w*f3.x; aB.w += w*f3.y;
    }
    sredA[tid] = aA; sredB[tid] = aB;
    __syncthreads();
    if (tid < 64) {
        float4 rA = sredA[tid], rB = sredB[tid];
        #pragma unroll
        for (int l = 1; l < 8; l++) {
            const float4 qA = sredA[l*64 + tid], qB = sredB[l*64 + tid];
            rA.x += qA.x; rA.y += qA.y; rA.z += qA.z; rA.w += qA.w;
            rB.x += qB.x; rB.y += qB.y; rB.z += qB.z; rB.w += qB.w;
        }
        float* o = out + b*D_ + tid*8;
        atomicAdd(o+0, rA.x); atomicAdd(o+1, rA.y);
        atomicAdd(o+2, rA.z); atomicAdd(o+3, rA.w);
        atomicAdd(o+4, rB.x); atomicAdd(o+5, rB.y);
        atomicAdd(o+6, rB.z); atomicAdd(o+7, rB.w);
    }
}

// ---------------- launch ----------------
extern "C" void kernel_launch(void* const* d_in, const int* in_sizes, int n_in,
                              void* d_out, int out_size)
{
    const float* query  = (const float*)d_in[0];
    const float* values = (const float*)d_in[1];
    const float* W1w    = (const float*)d_in[2];
    const float* W1b    = (const float*)d_in[3];
    const float* W2w    = (const float*)d_in[4];
    const float* W2b    = (const float*)d_in[5];
    const float* Vw     = (const float*)d_in[6];
    const float* Vb     = (const float*)d_in[7];
    float* out = (float*)d_out;

    cudaFuncSetAttribute(score_kernel, cudaFuncAttributeMaxDynamicSharedMemorySize, SM_TOTAL);

    convert_kernel<<<(B_*T_*D_)/(256*8), 256>>>((const float4*)values);
    qproj_kernel<<<dim3(B_, 4), 512>>>(query, W1w);
    transpose_kernel<<<dim3(U_/32, D_/32), dim3(32, 8)>>>(W2w, out);
    score_kernel<<<dim3(N_UT, T_/BM, B_), 256, SM_TOTAL>>>(W1b, W2b, Vw);
    softmax_kernel<<<B_, 512>>>(Vb, out);
    context_kernel<<<dim3(B_, T_/256), 512>>>(out);
}

// round 14
// speedup vs baseline: 1.1239x; 1.1239x over previous
#include <cuda_runtime.h>
#include <cuda_fp16.h>
#include <cstdint>
#include <cstddef>

#define B_ 32
#define T_ 2048
#define D_ 512
#define U_ 512
#define CTX_OFF (B_*D_)   // context at [0:16384], attn at [16384:]

// score-GEMM tiling: fp16 mma.sync m16n8k16, 256 threads, warp tile 64x32
// 3-stage cp.async pipeline, SW128 XOR-swizzled tiles (128B rows, no pad)
#define BM 128
#define BN 128
#define BK 64
#define NKC (D_/BK)       // 8 chunks
#define N_UT (U_/BN)      // 4 u-tiles

// dynamic smem for score kernel
#define SM_QP    0                      // 128 floats
#define SM_VW    512                    // 128 floats
#define SM_RED   1024                   // ssum[4][128] floats = 2048B
#define SM_A0    4096
#define SM_TILE  (BM*128)               // 16384 B (A or B, swizzled 128B rows)
#define SM_STAGE (2*SM_TILE)            // 32768 B
#define SM_TOTAL (SM_A0 + 3*SM_STAGE)   // 102400 B -> 2 CTAs/SM (200KB + static)

// ---------------- device scratch ----------------
__device__ __half g_vhalf[(size_t)B_*T_*D_];   // fp16 copy of values (67 MB)
__device__ __half g_W2Th[U_*D_];               // W2^T in fp16: [u][d]
__device__ float  g_qpart[4*B_*U_];
__device__ float  g_pscore[N_UT*B_*T_];

// ---------------- helpers ----------------
__device__ __forceinline__ uint32_t h2_as_u32(__half2 h){
    uint32_t u; __builtin_memcpy(&u, &h, 4); return u;
}
__device__ __forceinline__ float tanh_fast(float x){
    float r; asm("tanh.approx.f32 %0, %1;" : "=f"(r) : "f"(x)); return r;
}
__device__ __forceinline__ void cp16(uint32_t smem, const void* gmem){
    asm volatile("cp.async.cg.shared.global [%0], [%1], 16;\n" :: "r"(smem), "l"(gmem));
}
__device__ __forceinline__ void ldm_x4(uint32_t r[4], uint32_t addr){
    asm volatile("ldmatrix.sync.aligned.m8n8.x4.shared.b16 {%0,%1,%2,%3}, [%4];"
        : "=r"(r[0]), "=r"(r[1]), "=r"(r[2]), "=r"(r[3]) : "r"(addr));
}
__device__ __forceinline__ void mma_f16(float c[4], const uint32_t a[4],
                                        uint32_t b0, uint32_t b1){
    asm volatile(
        "mma.sync.aligned.m16n8k16.row.col.f32.f16.f16.f32 "
        "{%0,%1,%2,%3}, {%4,%5,%6,%7}, {%8,%9}, {%0,%1,%2,%3};\n"
        : "+f"(c[0]), "+f"(c[1]), "+f"(c[2]), "+f"(c[3])
        : "r"(a[0]), "r"(a[1]), "r"(a[2]), "r"(a[3]),
          "r"(b0), "r"(b1));
}

// ---------------- kernel 0: values fp32 -> fp16 ----------------
__global__ __launch_bounds__(256) void convert_kernel(const float4* __restrict__ v)
{
    const size_t i = (size_t)blockIdx.x*256 + threadIdx.x;   // 8 floats each
    const float4 f0 = v[2*i], f1 = v[2*i+1];
    uint4 o;
    o.x = h2_as_u32(__floats2half2_rn(f0.x, f0.y));
    o.y = h2_as_u32(__floats2half2_rn(f0.z, f0.w));
    o.z = h2_as_u32(__floats2half2_rn(f1.x, f1.y));
    o.w = h2_as_u32(__floats2half2_rn(f1.z, f1.w));
    ((uint4*)g_vhalf)[i] = o;
}

// ---------------- kernel 1: qproj partials over D-slices ----------------
__global__ __launch_bounds__(512) void qproj_kernel(
    const float* __restrict__ query, const float* __restrict__ W1)
{
    const int b = blockIdx.x, sp = blockIdx.y, tid = threadIdx.x;
    __shared__ float sq[128];
    if (tid < 128) sq[tid] = query[b*D_ + sp*128 + tid];
    __syncthreads();
    const float* w = W1 + (size_t)(sp*128)*U_ + tid;
    float acc = 0.f;
    #pragma unroll 8
    for (int d = 0; d < 128; d++)
        acc += sq[d] * w[(size_t)d*U_];
    g_qpart[(size_t)sp*(B_*U_) + b*U_ + tid] = acc;
}

// ---------------- kernel 1b: W2Th[u][d] = half(W2[d][u]); zero context ----------------
__global__ __launch_bounds__(256) void transpose_kernel(
    const float* __restrict__ W2, float* __restrict__ out)
{
    __shared__ float tile[32][33];
    const int bx = blockIdx.x*32, by = blockIdx.y*32;
    const int tx = threadIdx.x, ty = threadIdx.y;
    #pragma unroll
    for (int j = 0; j < 32; j += 8)
        tile[ty+j][tx] = W2[(size_t)(by+ty+j)*U_ + bx+tx];
    __syncthreads();
    #pragma unroll
    for (int j = 0; j < 32; j += 8)
        g_W2Th[(size_t)(bx+ty+j)*D_ + by+tx] = __float2half_rn(tile[tx][ty+j]);
    const int gid = (blockIdx.y*(U_/32) + blockIdx.x)*256 + ty*32 + tx;
    if (gid < CTX_OFF) out[gid] = 0.0f;
}

// ---------------- kernel 2: fused score GEMM (fp16 mma + ldmatrix, 3-stage, swizzled) ----------------
__global__ __launch_bounds__(256, 2) void score_kernel(
    const float* __restrict__ W1b, const float* __restrict__ W2b,
    const float* __restrict__ Vw)
{
    extern __shared__ __align__(1024) char smem[];
    float* sQP  = (float*)(smem + SM_QP);
    float* sVw  = (float*)(smem + SM_VW);
    float* ssum = (float*)(smem + SM_RED);

    const int tid = threadIdx.x;
    const int ut = blockIdx.x;
    const int t0 = blockIdx.y * BM;
    const int b  = blockIdx.z;
    const int u0 = ut * BN;
    const int warp = tid >> 5, lane = tid & 31;
    const int g = lane >> 2, tg = lane & 3;
    const int wm = warp >> 2, wn = warp & 3;     // 2 x 4 warps
    const int m0 = wm * 64,  n0 = wn * 32;

    if (tid < BN) {
        const int u = u0 + tid;
        sQP[tid] = g_qpart[u + b*U_] + g_qpart[B_*U_ + u + b*U_]
                 + g_qpart[2*B_*U_ + u + b*U_] + g_qpart[3*B_*U_ + u + b*U_]
                 + W1b[u] + W2b[u];
    } else {
        sVw[tid - BN] = Vw[u0 + tid - BN];
    }

    const __half* Abase = g_vhalf + ((size_t)b*T_ + t0) * D_;
    const __half* Bbase = g_W2Th + (size_t)u0 * D_;
    const uint32_t sA = (uint32_t)__cvta_generic_to_shared(smem + SM_A0);

    // ldmatrix lane geometry (rows + 16B-segment, swizzle applied per ks)
    const int arow = m0 + (lane & 15);
    const int aseg = (lane >> 4) & 1;            // 0 or 1 (cols 0-7 / 8-15)
    const int brow = n0 + (lane & 7) + ((lane & 16) >> 1);
    const int bseg = (lane >> 3) & 1;
    const int sxA = arow & 7, sxB = brow & 7;    // per-row swizzle XOR

    float c[4][4][4];
    #pragma unroll
    for (int mi = 0; mi < 4; mi++)
        #pragma unroll
        for (int ni = 0; ni < 4; ni++)
            #pragma unroll
            for (int q = 0; q < 4; q++) c[mi][ni][q] = 0.f;

    // per stage: A 128 rows x 8 segs + B same; 256 threads x 4 iters each
    #define LOADC(KC, S) do {                                                    \
        const uint32_t as_ = sA + (S)*SM_STAGE;                                  \
        const uint32_t bs_ = as_ + SM_TILE;                                      \
        _Pragma("unroll")                                                        \
        for (int j = 0; j < 4; j++) {                                            \
            int idx = tid + j*256, r = idx >> 3, cs = idx & 7;                   \
            uint32_t off = r*128 + (uint32_t)((cs ^ (r & 7)) << 4);              \
            cp16(as_ + off, Abase + (size_t)r*D_ + (KC)*BK + cs*8);              \
            cp16(bs_ + off, Bbase + (size_t)r*D_ + (KC)*BK + cs*8);              \
        }                                                                        \
        asm volatile("cp.async.commit_group;\n");                                \
    } while (0)

    LOADC(0, 0);
    LOADC(1, 1);

    for (int kc = 0; kc < NKC; kc++) {
        if (kc < NKC-1) asm volatile("cp.async.wait_group 1;\n");
        else            asm volatile("cp.async.wait_group 0;\n");
        __syncthreads();                 // stage (kc-1)%3 fully drained by all warps
        if (kc + 2 < NKC) LOADC(kc + 2, (kc + 2) % 3);   // overlap with compute below

        const int s = kc % 3;
        const uint32_t as_ = sA + s*SM_STAGE;
        const uint32_t bs_ = as_ + SM_TILE;

        #pragma unroll
        for (int ks = 0; ks < BK; ks += 16) {
            const int segA = (ks >> 3) + aseg;
            const int segB = (ks >> 3) + bseg;
            const uint32_t offA = (uint32_t)((segA ^ sxA) << 4);
            const uint32_t offB = (uint32_t)((segB ^ sxB) << 4);
            uint32_t a[4][4], bb[2][4];
            ldm_x4(a[0],  as_ + (arow     )*128 + offA);
            ldm_x4(a[1],  as_ + (arow + 16)*128 + offA);
            ldm_x4(a[2],  as_ + (arow + 32)*128 + offA);
            ldm_x4(a[3],  as_ + (arow + 48)*128 + offA);
            ldm_x4(bb[0], bs_ + (brow     )*128 + offB);
            ldm_x4(bb[1], bs_ + (brow + 16)*128 + offB);
            #pragma unroll
            for (int mi = 0; mi < 4; mi++)
                #pragma unroll
                for (int ni = 0; ni < 4; ni++)
                    mma_f16(c[mi][ni], a[mi],
                            bb[ni>>1][2*(ni&1)], bb[ni>>1][2*(ni&1)+1]);
        }
    }
    #undef LOADC

    // ---- epilogue: tanh + dot(Vw), reduce over u ----
    float rs[4][2] = {{0.f,0.f},{0.f,0.f},{0.f,0.f},{0.f,0.f}};
    #pragma unroll
    for (int mi = 0; mi < 4; mi++)
        #pragma unroll
        for (int ni = 0; ni < 4; ni++) {
            const int cN0 = n0 + ni*8 + 2*tg;
            #pragma unroll
            for (int h = 0; h < 2; h++)
                #pragma unroll
                for (int q = 0; q < 2; q++) {
                    float v = c[mi][ni][h*2 + q] + sQP[cN0 + q];
                    rs[mi][h] += tanh_fast(v) * sVw[cN0 + q];
                }
        }
    #pragma unroll
    for (int mi = 0; mi < 4; mi++)
        #pragma unroll
        for (int h = 0; h < 2; h++) {
            rs[mi][h] += __shfl_xor_sync(0xffffffffu, rs[mi][h], 1);
            rs[mi][h] += __shfl_xor_sync(0xffffffffu, rs[mi][h], 2);
        }
    __syncthreads();   // all compute done before ssum reuse
    if (tg == 0) {
        #pragma unroll
        for (int mi = 0; mi < 4; mi++)
            #pragma unroll
            for (int h = 0; h < 2; h++)
                ssum[wn*BM + m0 + mi*16 + h*8 + g] = rs[mi][h];
    }
    __syncthreads();
    if (tid < BM) {
        float s = ssum[tid] + ssum[BM + tid] + ssum[2*BM + tid] + ssum[3*BM + tid];
        g_pscore[(size_t)ut*(B_*T_) + b*T_ + t0 + tid] = s;
    }
}

// ---------------- kernel 3: softmax over T, write attn ----------------
__global__ __launch_bounds__(512) void softmax_kernel(
    const float* __restrict__ Vb, float* __restrict__ out)
{
    const int b = blockIdx.x, tid = threadIdx.x;
    __shared__ float red[512];
    float loc[4];
    const float vb = Vb[0];
    float mx = -1e30f;
    #pragma unroll
    for (int j = 0; j < 4; j++) {
        int t = tid + j*512;
        float s = vb;
        #pragma unroll
        for (int i = 0; i < N_UT; i++) s += g_pscore[i*(B_*T_) + b*T_ + t];
        loc[j] = s;
        mx = fmaxf(mx, s);
    }
    red[tid] = mx; __syncthreads();
    #pragma unroll
    for (int s = 256; s > 0; s >>= 1) {
        if (tid < s) red[tid] = fmaxf(red[tid], red[tid + s]);
        __syncthreads();
    }
    mx = red[0]; __syncthreads();
    float se = 0.f;
    #pragma unroll
    for (int j = 0; j < 4; j++) { loc[j] = __expf(loc[j] - mx); se += loc[j]; }
    red[tid] = se; __syncthreads();
    #pragma unroll
    for (int s = 256; s > 0; s >>= 1) {
        if (tid < s) red[tid] += red[tid + s];
        __syncthreads();
    }
    const float inv = 1.0f / red[0];
    #pragma unroll
    for (int j = 0; j < 4; j++)
        out[CTX_OFF + b*T_ + tid + j*512] = loc[j] * inv;
}

// ---------------- kernel 4: context = sum_t attn * values (fp16 values) ----------------
__global__ __launch_bounds__(512) void context_kernel(float* __restrict__ out)
{
    const int b = blockIdx.x, tid = threadIdx.x;
    const int t0 = blockIdx.y * 256;
    const int tl = tid >> 6;          // t-lane 0..7
    const int dt = tid & 63;          // d-group: 8 halfs each
    __shared__ float sa[256];
    __shared__ float4 sredA[512];
    __shared__ float4 sredB[512];
    if (tid < 256) sa[tid] = out[CTX_OFF + b*T_ + t0 + tid];
    __syncthreads();
    const uint4* vp = (const uint4*)(g_vhalf + ((size_t)b*T_ + t0)*D_) + dt;
    float4 aA = {0.f,0.f,0.f,0.f}, aB = {0.f,0.f,0.f,0.f};
    #pragma unroll 4
    for (int tt = tl; tt < 256; tt += 8) {
        const uint4 u = vp[(size_t)tt*(D_/8)];
        const float w = sa[tt];
        const float2 f0 = __half22float2(*(const __half2*)&u.x);
        const float2 f1 = __half22float2(*(const __half2*)&u.y);
        const float2 f2 = __half22float2(*(const __half2*)&u.z);
        const float2 f3 = __half22float2(*(const __half2*)&u.w);
        aA.x += w*f0.x; aA.y += w*f0.y; aA.z += w*f1.x; aA.w += w*f1.y;
        aB.x += w*f2.x; aB.y += w*f2.y; aB.z += w*f3.x; aB.w += w*f3.y;
    }
    sredA[tid] = aA; sredB[tid] = aB;
    __syncthreads();
    if (tid < 64) {
        float4 rA = sredA[tid], rB = sredB[tid];
        #pragma unroll
        for (int l = 1; l < 8; l++) {
            const float4 qA = sredA[l*64 + tid], qB = sredB[l*64 + tid];
            rA.x += qA.x; rA.y += qA.y; rA.z += qA.z; rA.w += qA.w;
            rB.x += qB.x; rB.y += qB.y; rB.z += qB.z; rB.w += qB.w;
        }
        float* o = out + b*D_ + tid*8;
        atomicAdd(o+0, rA.x); atomicAdd(o+1, rA.y);
        atomicAdd(o+2, rA.z); atomicAdd(o+3, rA.w);
        atomicAdd(o+4, rB.x); atomicAdd(o+5, rB.y);
        atomicAdd(o+6, rB.z); atomicAdd(o+7, rB.w);
    }
}

// ---------------- launch ----------------
extern "C" void kernel_launch(void* const* d_in, const int* in_sizes, int n_in,
                              void* d_out, int out_size)
{
    const float* query  = (const float*)d_in[0];
    const float* values = (const float*)d_in[1];
    const float* W1w    = (const float*)d_in[2];
    const float* W1b    = (const float*)d_in[3];
    const float* W2w    = (const float*)d_in[4];
    const float* W2b    = (const float*)d_in[5];
    const float* Vw     = (const float*)d_in[6];
    const float* Vb     = (const float*)d_in[7];
    float* out = (float*)d_out;

    cudaFuncSetAttribute(score_kernel, cudaFuncAttributeMaxDynamicSharedMemorySize, SM_TOTAL);

    convert_kernel<<<(B_*T_*D_)/(256*8), 256>>>((const float4*)values);
    qproj_kernel<<<dim3(B_, 4), 512>>>(query, W1w);
    transpose_kernel<<<dim3(U_/32, D_/32), dim3(32, 8)>>>(W2w, out);
    score_kernel<<<dim3(N_UT, T_/BM, B_), 256, SM_TOTAL>>>(W1b, W2b, Vw);
    softmax_kernel<<<B_, 512>>>(Vb, out);
    context_kernel<<<dim3(B_, T_/256), 512>>>(out);
}

// round 15
// speedup vs baseline: 1.2784x; 1.1375x over previous
#include <cuda_runtime.h>
#include <cuda_fp16.h>
#include <cstdint>
#include <cstddef>

#define B_ 32
#define T_ 2048
#define D_ 512
#define U_ 512
#define CTX_OFF (B_*D_)   // context at [0:16384], attn at [16384:]

// score-GEMM tiling: fp16 mma.sync m16n8k16, 256 threads, warp tile 64x32
// 3-stage cp.async pipeline, SW128 XOR-swizzled tiles (128B rows, no pad)
#define BM 128
#define BN 128
#define BK 64
#define NKC (D_/BK)       // 8 chunks
#define N_UT (U_/BN)      // 4 u-tiles

// dynamic smem for score kernel
#define SM_QP    0                      // 128 floats
#define SM_VW    512                    // 128 floats
#define SM_RED   1024                   // ssum[4][128] floats = 2048B
#define SM_A0    4096
#define SM_TILE  (BM*128)               // 16384 B (A or B, swizzled 128B rows)
#define SM_STAGE (2*SM_TILE)            // 32768 B
#define SM_TOTAL (SM_A0 + 3*SM_STAGE)   // 102400 B -> 2 CTAs/SM

// prep kernel block roles
#define PREP_QPROJ  128                         // blocks 0..127: qproj (b = bid>>2, sp = bid&3)
#define PREP_TRANS  (PREP_QPROJ + 256)          // 128..383: W2 transpose + zero ctx
#define PREP_TOTAL  (PREP_TRANS + (B_*T_*D_)/(256*8))   // + 8192 convert blocks

// ---------------- device scratch ----------------
__device__ __half g_vhalf[(size_t)B_*T_*D_];   // fp16 copy of values (67 MB)
__device__ __half g_W2Th[U_*D_];               // W2^T in fp16: [u][d]
__device__ float  g_qpart[4*B_*U_];
__device__ float  g_pscore[N_UT*B_*T_];

// ---------------- helpers ----------------
__device__ __forceinline__ uint32_t h2_as_u32(__half2 h){
    uint32_t u; __builtin_memcpy(&u, &h, 4); return u;
}
__device__ __forceinline__ float tanh_fast(float x){
    float r; asm("tanh.approx.f32 %0, %1;" : "=f"(r) : "f"(x)); return r;
}
__device__ __forceinline__ void cp16(uint32_t smem, const void* gmem){
    asm volatile("cp.async.cg.shared.global [%0], [%1], 16;\n" :: "r"(smem), "l"(gmem));
}
__device__ __forceinline__ void ldm_x4(uint32_t r[4], uint32_t addr){
    asm volatile("ldmatrix.sync.aligned.m8n8.x4.shared.b16 {%0,%1,%2,%3}, [%4];"
        : "=r"(r[0]), "=r"(r[1]), "=r"(r[2]), "=r"(r[3]) : "r"(addr));
}
__device__ __forceinline__ void mma_f16(float c[4], const uint32_t a[4],
                                        uint32_t b0, uint32_t b1){
    asm volatile(
        "mma.sync.aligned.m16n8k16.row.col.f32.f16.f16.f32 "
        "{%0,%1,%2,%3}, {%4,%5,%6,%7}, {%8,%9}, {%0,%1,%2,%3};\n"
        : "+f"(c[0]), "+f"(c[1]), "+f"(c[2]), "+f"(c[3])
        : "r"(a[0]), "r"(a[1]), "r"(a[2]), "r"(a[3]),
          "r"(b0), "r"(b1));
}

// ---------------- kernel 1: prep = qproj + W2 transpose + values fp32->fp16 ----------------
// Small roles scheduled first, convert blocks stream DRAM behind them.
__global__ __launch_bounds__(256) void prep_kernel(
    const float4* __restrict__ values4, const float* __restrict__ query,
    const float* __restrict__ W1,       const float* __restrict__ W2,
    float* __restrict__ out)
{
    const int bid = blockIdx.x, tid = threadIdx.x;

    if (bid < PREP_QPROJ) {
        // ---- qproj partials: b = bid>>2, D-slice sp = bid&3; 256 thr, 2 u each ----
        const int b = bid >> 2, sp = bid & 3;
        __shared__ float sq[128];
        if (tid < 128) sq[tid] = query[b*D_ + sp*128 + tid];
        __syncthreads();
        const float* w = W1 + (size_t)(sp*128)*U_ + tid;
        float a0 = 0.f, a1 = 0.f;
        #pragma unroll 8
        for (int d = 0; d < 128; d++) {
            const float q = sq[d];
            a0 += q * w[(size_t)d*U_];
            a1 += q * w[(size_t)d*U_ + 256];
        }
        g_qpart[(size_t)sp*(B_*U_) + b*U_ + tid]       = a0;
        g_qpart[(size_t)sp*(B_*U_) + b*U_ + tid + 256] = a1;
    } else if (bid < PREP_TRANS) {
        // ---- W2Th[u][d] = half(W2[d][u]); zero context region ----
        const int tb = bid - PREP_QPROJ;           // 0..255
        const int bx = (tb & 15)*32, by = (tb >> 4)*32;
        const int tx = tid & 31, ty = tid >> 5;    // 32 x 8
        __shared__ float tile[32][33];
        #pragma unroll
        for (int j = 0; j < 32; j += 8)
            tile[ty+j][tx] = W2[(size_t)(by+ty+j)*U_ + bx+tx];
        __syncthreads();
        #pragma unroll
        for (int j = 0; j < 32; j += 8)
            g_W2Th[(size_t)(bx+ty+j)*D_ + by+tx] = __float2half_rn(tile[tx][ty+j]);
        const int gid = tb*256 + tid;
        if (gid < CTX_OFF) out[gid] = 0.0f;
    } else {
        // ---- convert: 8 floats per thread ----
        const size_t i = (size_t)(bid - PREP_TRANS)*256 + tid;
        const float4 f0 = values4[2*i], f1 = values4[2*i+1];
        uint4 o;
        o.x = h2_as_u32(__floats2half2_rn(f0.x, f0.y));
        o.y = h2_as_u32(__floats2half2_rn(f0.z, f0.w));
        o.z = h2_as_u32(__floats2half2_rn(f1.x, f1.y));
        o.w = h2_as_u32(__floats2half2_rn(f1.z, f1.w));
        ((uint4*)g_vhalf)[i] = o;
    }
}

// ---------------- kernel 2: fused score GEMM (fp16 mma + ldmatrix, 3-stage, swizzled) ----------------
__global__ __launch_bounds__(256, 2) void score_kernel(
    const float* __restrict__ W1b, const float* __restrict__ W2b,
    const float* __restrict__ Vw)
{
    extern __shared__ __align__(1024) char smem[];
    float* sQP  = (float*)(smem + SM_QP);
    float* sVw  = (float*)(smem + SM_VW);
    float* ssum = (float*)(smem + SM_RED);

    const int tid = threadIdx.x;
    const int ut = blockIdx.x;
    const int t0 = blockIdx.y * BM;
    const int b  = blockIdx.z;
    const int u0 = ut * BN;
    const int warp = tid >> 5, lane = tid & 31;
    const int g = lane >> 2, tg = lane & 3;
    const int wm = warp >> 2, wn = warp & 3;     // 2 x 4 warps
    const int m0 = wm * 64,  n0 = wn * 32;

    if (tid < BN) {
        const int u = u0 + tid;
        sQP[tid] = g_qpart[u + b*U_] + g_qpart[B_*U_ + u + b*U_]
                 + g_qpart[2*B_*U_ + u + b*U_] + g_qpart[3*B_*U_ + u + b*U_]
                 + W1b[u] + W2b[u];
    } else {
        sVw[tid - BN] = Vw[u0 + tid - BN];
    }

    const __half* Abase = g_vhalf + ((size_t)b*T_ + t0) * D_;
    const __half* Bbase = g_W2Th + (size_t)u0 * D_;
    const uint32_t sA = (uint32_t)__cvta_generic_to_shared(smem + SM_A0);

    // ldmatrix lane geometry (rows + 16B-segment, swizzle applied per ks)
    const int arow = m0 + (lane & 15);
    const int aseg = (lane >> 4) & 1;            // 0 or 1 (cols 0-7 / 8-15)
    const int brow = n0 + (lane & 7) + ((lane & 16) >> 1);
    const int bseg = (lane >> 3) & 1;
    const int sxA = arow & 7, sxB = brow & 7;    // per-row swizzle XOR

    float c[4][4][4];
    #pragma unroll
    for (int mi = 0; mi < 4; mi++)
        #pragma unroll
        for (int ni = 0; ni < 4; ni++)
            #pragma unroll
            for (int q = 0; q < 4; q++) c[mi][ni][q] = 0.f;

    // per stage: A 128 rows x 8 segs + B same; 256 threads x 4 iters each
    #define LOADC(KC, S) do {                                                    \
        const uint32_t as_ = sA + (S)*SM_STAGE;                                  \
        const uint32_t bs_ = as_ + SM_TILE;                                      \
        _Pragma("unroll")                                                        \
        for (int j = 0; j < 4; j++) {                                            \
            int idx = tid + j*256, r = idx >> 3, cs = idx & 7;                   \
            uint32_t off = r*128 + (uint32_t)((cs ^ (r & 7)) << 4);              \
            cp16(as_ + off, Abase + (size_t)r*D_ + (KC)*BK + cs*8);              \
            cp16(bs_ + off, Bbase + (size_t)r*D_ + (KC)*BK + cs*8);              \
        }                                                                        \
        asm volatile("cp.async.commit_group;\n");                                \
    } while (0)

    LOADC(0, 0);
    LOADC(1, 1);

    for (int kc = 0; kc < NKC; kc++) {
        if (kc < NKC-1) asm volatile("cp.async.wait_group 1;\n");
        else            asm volatile("cp.async.wait_group 0;\n");
        __syncthreads();                 // stage (kc-1)%3 fully drained by all warps
        if (kc + 2 < NKC) LOADC(kc + 2, (kc + 2) % 3);   // overlap with compute below

        const int s = kc % 3;
        const uint32_t as_ = sA + s*SM_STAGE;
        const uint32_t bs_ = as_ + SM_TILE;

        #pragma unroll
        for (int ks = 0; ks < BK; ks += 16) {
            const int segA = (ks >> 3) + aseg;
            const int segB = (ks >> 3) + bseg;
            const uint32_t offA = (uint32_t)((segA ^ sxA) << 4);
            const uint32_t offB = (uint32_t)((segB ^ sxB) << 4);
            uint32_t a[4][4], bb[2][4];
            ldm_x4(a[0],  as_ + (arow     )*128 + offA);
            ldm_x4(a[1],  as_ + (arow + 16)*128 + offA);
            ldm_x4(a[2],  as_ + (arow + 32)*128 + offA);
            ldm_x4(a[3],  as_ + (arow + 48)*128 + offA);
            ldm_x4(bb[0], bs_ + (brow     )*128 + offB);
            ldm_x4(bb[1], bs_ + (brow + 16)*128 + offB);
            #pragma unroll
            for (int mi = 0; mi < 4; mi++)
                #pragma unroll
                for (int ni = 0; ni < 4; ni++)
                    mma_f16(c[mi][ni], a[mi],
                            bb[ni>>1][2*(ni&1)], bb[ni>>1][2*(ni&1)+1]);
        }
    }
    #undef LOADC

    // ---- epilogue: tanh + dot(Vw), reduce over u ----
    float rs[4][2] = {{0.f,0.f},{0.f,0.f},{0.f,0.f},{0.f,0.f}};
    #pragma unroll
    for (int mi = 0; mi < 4; mi++)
        #pragma unroll
        for (int ni = 0; ni < 4; ni++) {
            const int cN0 = n0 + ni*8 + 2*tg;
            #pragma unroll
            for (int h = 0; h < 2; h++)
                #pragma unroll
                for (int q = 0; q < 2; q++) {
                    float v = c[mi][ni][h*2 + q] + sQP[cN0 + q];
                    rs[mi][h] += tanh_fast(v) * sVw[cN0 + q];
                }
        }
    #pragma unroll
    for (int mi = 0; mi < 4; mi++)
        #pragma unroll
        for (int h = 0; h < 2; h++) {
            rs[mi][h] += __shfl_xor_sync(0xffffffffu, rs[mi][h], 1);
            rs[mi][h] += __shfl_xor_sync(0xffffffffu, rs[mi][h], 2);
        }
    __syncthreads();   // all compute done before ssum reuse
    if (tg == 0) {
        #pragma unroll
        for (int mi = 0; mi < 4; mi++)
            #pragma unroll
            for (int h = 0; h < 2; h++)
                ssum[wn*BM + m0 + mi*16 + h*8 + g] = rs[mi][h];
    }
    __syncthreads();
    if (tid < BM) {
        float s = ssum[tid] + ssum[BM + tid] + ssum[2*BM + tid] + ssum[3*BM + tid];
        g_pscore[(size_t)ut*(B_*T_) + b*T_ + t0 + tid] = s;
    }
}

// ---------------- kernel 3: softmax over T (shuffle reductions), write attn ----------------
__global__ __launch_bounds__(512) void softmax_kernel(
    const float* __restrict__ Vb, float* __restrict__ out)
{
    const int b = blockIdx.x, tid = threadIdx.x;
    const int lane = tid & 31, wid = tid >> 5;
    __shared__ float red[16];
    float loc[4];
    const float vb = Vb[0];
    float mx = -1e30f;
    #pragma unroll
    for (int j = 0; j < 4; j++) {
        int t = tid + j*512;
        float s = vb;
        #pragma unroll
        for (int i = 0; i < N_UT; i++) s += g_pscore[i*(B_*T_) + b*T_ + t];
        loc[j] = s;
        mx = fmaxf(mx, s);
    }
    #pragma unroll
    for (int o = 16; o > 0; o >>= 1) mx = fmaxf(mx, __shfl_xor_sync(0xffffffffu, mx, o));
    if (lane == 0) red[wid] = mx;
    __syncthreads();
    if (tid == 0) {
        float v = red[0];
        #pragma unroll
        for (int i = 1; i < 16; i++) v = fmaxf(v, red[i]);
        red[0] = v;
    }
    __syncthreads();
    mx = red[0];
    __syncthreads();
    float se = 0.f;
    #pragma unroll
    for (int j = 0; j < 4; j++) { loc[j] = __expf(loc[j] - mx); se += loc[j]; }
    #pragma unroll
    for (int o = 16; o > 0; o >>= 1) se += __shfl_xor_sync(0xffffffffu, se, o);
    if (lane == 0) red[wid] = se;
    __syncthreads();
    if (tid == 0) {
        float v = red[0];
        #pragma unroll
        for (int i = 1; i < 16; i++) v += red[i];
        red[0] = v;
    }
    __syncthreads();
    const float inv = 1.0f / red[0];
    #pragma unroll
    for (int j = 0; j < 4; j++)
        out[CTX_OFF + b*T_ + tid + j*512] = loc[j] * inv;
}

// ---------------- kernel 4: context = sum_t attn * values (fp16 values) ----------------
__global__ __launch_bounds__(512) void context_kernel(float* __restrict__ out)
{
    const int b = blockIdx.x, tid = threadIdx.x;
    const int t0 = blockIdx.y * 256;
    const int tl = tid >> 6;          // t-lane 0..7
    const int dt = tid & 63;          // d-group: 8 halfs each
    __shared__ float sa[256];
    __shared__ float4 sredA[512];
    __shared__ float4 sredB[512];
    if (tid < 256) sa[tid] = out[CTX_OFF + b*T_ + t0 + tid];
    __syncthreads();
    const uint4* vp = (const uint4*)(g_vhalf + ((size_t)b*T_ + t0)*D_) + dt;
    float4 aA = {0.f,0.f,0.f,0.f}, aB = {0.f,0.f,0.f,0.f};
    #pragma unroll 4
    for (int tt = tl; tt < 256; tt += 8) {
        const uint4 u = vp[(size_t)tt*(D_/8)];
        const float w = sa[tt];
        const float2 f0 = __half22float2(*(const __half2*)&u.x);
        const float2 f1 = __half22float2(*(const __half2*)&u.y);
        const float2 f2 = __half22float2(*(const __half2*)&u.z);
        const float2 f3 = __half22float2(*(const __half2*)&u.w);
        aA.x += w*f0.x; aA.y += w*f0.y; aA.z += w*f1.x; aA.w += w*f1.y;
        aB.x += w*f2.x; aB.y += w*f2.y; aB.z += w*f3.x; aB.w += w*f3.y;
    }
    sredA[tid] = aA; sredB[tid] = aB;
    __syncthreads();
    if (tid < 64) {
        float4 rA = sredA[tid], rB = sredB[tid];
        #pragma unroll
        for (int l = 1; l < 8; l++) {
            const float4 qA = sredA[l*64 + tid], qB = sredB[l*64 + tid];
            rA.x += qA.x; rA.y += qA.y; rA.z += qA.z; rA.w += qA.w;
            rB.x += qB.x; rB.y += qB.y; rB.z += qB.z; rB.w += qB.w;
        }
        float* o = out + b*D_ + tid*8;
        atomicAdd(o+0, rA.x); atomicAdd(o+1, rA.y);
        atomicAdd(o+2, rA.z); atomicAdd(o+3, rA.w);
        atomicAdd(o+4, rB.x); atomicAdd(o+5, rB.y);
        atomicAdd(o+6, rB.z); atomicAdd(o+7, rB.w);
    }
}

// ---------------- launch ----------------
extern "C" void kernel_launch(void* const* d_in, const int* in_sizes, int n_in,
                              void* d_out, int out_size)
{
    const float* query  = (const float*)d_in[0];
    const float* values = (const float*)d_in[1];
    const float* W1w    = (const float*)d_in[2];
    const float* W1b    = (const float*)d_in[3];
    const float* W2w    = (const float*)d_in[4];
    const float* W2b    = (const float*)d_in[5];
    const float* Vw     = (const float*)d_in[6];
    const float* Vb     = (const float*)d_in[7];
    float* out = (float*)d_out;

    cudaFuncSetAttribute(score_kernel, cudaFuncAttributeMaxDynamicSharedMemorySize, SM_TOTAL);

    prep_kernel<<<PREP_TOTAL, 256>>>((const float4*)values, query, W1w, W2w, out);
    score_kernel<<<dim3(N_UT, T_/BM, B_), 256, SM_TOTAL>>>(W1b, W2b, Vw);
    softmax_kernel<<<B_, 512>>>(Vb, out);
    context_kernel<<<dim3(B_, T_/256), 512>>>(out);
}